// round 2
// baseline (speedup 1.0000x reference)
#include <cuda_runtime.h>

#define NN 4
#define HH 480
#define WW 640

// Scratch (static device arrays; no allocation anywhere)
__device__ float  g_t1[NN * 4 * HH * WW];   // ping
__device__ float  g_t2[NN * 4 * HH * WW];   // pong / theta NHWC4
__device__ float4 g_xt[NN * HH * WW];       // x packed NHWC (c=0..2, w=0)

// ---------------------------------------------------------------------------
// Kernel 0: pack x [N,3,H,W] -> NHWC float4 (4th lane zero)
// ---------------------------------------------------------------------------
__global__ void __launch_bounds__(256) pack_x_kernel(const float* __restrict__ x) {
    int idx = blockIdx.x * 256 + threadIdx.x;
    const int total = NN * HH * WW;
    if (idx >= total) return;
    int n  = idx / (HH * WW);
    int hw = idx - n * (HH * WW);
    const float* xb = x + (size_t)n * 3 * HH * WW + hw;
    float4 v;
    v.x = __ldg(&xb[0]);
    v.y = __ldg(&xb[HH * WW]);
    v.z = __ldg(&xb[2 * HH * WW]);
    v.w = 0.f;
    g_xt[idx] = v;
}

// ---------------------------------------------------------------------------
// 5x5 conv, pad 2, OC=4. Tile 128x8 outputs per CTA (block 32x8, 4 px/thread).
// SRC/DST select input/output buffers: 0 = external (x / unused), 1 = g_t1, 2 = g_t2.
// NHWC_OUT: write [N,H,W,4] float4 into g_t2 (for the final theta conv).
// ---------------------------------------------------------------------------
template <int IC, int SRC, int DST, bool NHWC_OUT>
__global__ void __launch_bounds__(256) conv5_kernel(
    const float* __restrict__ xin, const float* __restrict__ w,
    const float* __restrict__ b)
{
    __shared__ float tile[IC][12][132];
    __shared__ float wsh[IC][4][25];
    __shared__ float bsh[4];

    const int tx  = threadIdx.x;
    const int ty  = threadIdx.y;
    const int tid = ty * 32 + tx;
    const int x0  = blockIdx.x * 128;
    const int y0  = blockIdx.y * 8;
    const int n   = blockIdx.z;

    const float* in = (SRC == 0) ? xin : (SRC == 1) ? g_t1 : g_t2;
    float* out      = (DST == 1) ? g_t1 : g_t2;

    // weights: w layout [OC=4][IC][5][5] -> wsh[ic][oc][k]
    for (int i = tid; i < IC * 100; i += 256) {
        int ic  = i / 100;
        int rem = i - ic * 100;
        int oc  = rem / 25;
        int k   = rem - oc * 25;
        wsh[ic][oc][k] = __ldg(&w[(oc * IC + ic) * 25 + k]);
    }
    if (tid < 4) bsh[tid] = __ldg(&b[tid]);

    // input tile with halo: rows y0-2..y0+9, cols x0-2..x0+129
    const float* inb = in + (size_t)n * IC * HH * WW;
    for (int i = tid; i < IC * 12 * 132; i += 256) {
        int ic = i / (12 * 132);
        int r  = (i / 132) % 12;
        int c  = i % 132;
        int gy = y0 + r - 2;
        int gx = x0 + c - 2;
        float v = 0.f;
        if (gy >= 0 && gy < HH && gx >= 0 && gx < WW)
            v = __ldg(&inb[(size_t)ic * HH * WW + gy * WW + gx]);
        tile[ic][r][c] = v;
    }
    __syncthreads();

    float acc[4][4];
#pragma unroll
    for (int t = 0; t < 4; ++t) {
        acc[t][0] = bsh[0]; acc[t][1] = bsh[1];
        acc[t][2] = bsh[2]; acc[t][3] = bsh[3];
    }

#pragma unroll
    for (int ic = 0; ic < IC; ++ic) {
#pragma unroll
        for (int ky = 0; ky < 5; ++ky) {
            const float* trow = &tile[ic][ty + ky][tx];
#pragma unroll
            for (int kx = 0; kx < 5; ++kx) {
                const float w0 = wsh[ic][0][ky * 5 + kx];
                const float w1 = wsh[ic][1][ky * 5 + kx];
                const float w2 = wsh[ic][2][ky * 5 + kx];
                const float w3 = wsh[ic][3][ky * 5 + kx];
#pragma unroll
                for (int t = 0; t < 4; ++t) {
                    const float v = trow[t * 32 + kx];
                    acc[t][0] += v * w0;
                    acc[t][1] += v * w1;
                    acc[t][2] += v * w2;
                    acc[t][3] += v * w3;
                }
            }
        }
    }

    const int y = y0 + ty;
    if (NHWC_OUT) {
        float4* o4 = reinterpret_cast<float4*>(out);
#pragma unroll
        for (int t = 0; t < 4; ++t) {
            const int xx = x0 + tx + 32 * t;
            o4[(size_t)n * HH * WW + y * WW + xx] =
                make_float4(acc[t][0], acc[t][1], acc[t][2], acc[t][3]);
        }
    } else {
#pragma unroll
        for (int t = 0; t < 4; ++t) {
            const int xx = x0 + tx + 32 * t;
#pragma unroll
            for (int oc = 0; oc < 4; ++oc)
                out[((size_t)(n * 4 + oc) * HH + y) * WW + xx] = acc[t][oc];
        }
    }
}

// ---------------------------------------------------------------------------
// Fused: grid build + bilinear grid_sample + stride-3 3x3 conv epilogue.
// theta in NHWC float4 (g_t2). x in NHWC float4 (g_xt).
// Thread map: tx -> h (gathers coalesced along x columns), ty -> w.
// ---------------------------------------------------------------------------
__device__ __forceinline__ float4 fetch4(const float4* __restrict__ b, int x, int y) {
    if ((unsigned)x < (unsigned)WW && (unsigned)y < (unsigned)HH)
        return __ldg(&b[y * WW + x]);
    return make_float4(0.f, 0.f, 0.f, 0.f);
}

__global__ void __launch_bounds__(256) stn_sample_kernel(
    const float* __restrict__ wr, const float* __restrict__ br,
    float* __restrict__ out)
{
    __shared__ float wsh[81];
    __shared__ float bsh[3];
    __shared__ float so[3][32][9];

    const int tx  = threadIdx.x;
    const int ty  = threadIdx.y;
    const int tid = ty * 32 + tx;
    if (tid < 81) wsh[tid] = __ldg(&wr[tid]);
    if (tid < 3)  bsh[tid] = __ldg(&br[tid]);
    __syncthreads();

    const int h0 = blockIdx.x * 32;
    const int w0 = blockIdx.y * 8;
    const int n  = blockIdx.z;
    const int h  = h0 + tx;
    const int w  = w0 + ty;

    const float4* tb = reinterpret_cast<const float4*>(g_t2) + (size_t)n * HH * WW;
    const float4* xb = g_xt + (size_t)n * HH * WW;

    const float4 th = __ldg(&tb[h * WW + w]);

    const float yy = -1.f + 2.f * (float)h / (float)(HH - 1);
    const float xx = -1.f + 2.f * (float)w / (float)(WW - 1);

    float acc0 = 0.f, acc1 = 0.f, acc2 = 0.f;

#pragma unroll
    for (int i = 0; i < 3; ++i) {
        const float lyv = (float)(i - 1) * (3.0f / (float)HH);
#pragma unroll
        for (int j = 0; j < 3; ++j) {
            const float lxv = (float)(j - 1) * (3.0f / (float)WW);
            // final grid (follow reference convention exactly)
            const float gx = yy + th.x * lyv + th.y * lxv;   // grid[...,0] (x coord)
            const float gy = xx + th.z * lyv + th.w * lxv;   // grid[...,1] (y coord)
            const float ix = ((gx + 1.0f) * (float)WW - 1.0f) * 0.5f;
            const float iy = ((gy + 1.0f) * (float)HH - 1.0f) * 0.5f;
            const float ix0 = floorf(ix);
            const float iy0 = floorf(iy);
            const float wx1 = ix - ix0;
            const float wy1 = iy - iy0;
            const float wx0 = 1.0f - wx1;
            const float wy0 = 1.0f - wy1;
            const int xi = (int)ix0;
            const int yi = (int)iy0;

            const float4 v00 = fetch4(xb, xi,     yi);
            const float4 v10 = fetch4(xb, xi + 1, yi);
            const float4 v01 = fetch4(xb, xi,     yi + 1);
            const float4 v11 = fetch4(xb, xi + 1, yi + 1);

            const float w00 = wx0 * wy0, w10 = wx1 * wy0;
            const float w01 = wx0 * wy1, w11 = wx1 * wy1;

            const float vx = v00.x * w00 + v10.x * w10 + v01.x * w01 + v11.x * w11;
            const float vy = v00.y * w00 + v10.y * w10 + v01.y * w01 + v11.y * w11;
            const float vz = v00.z * w00 + v10.z * w10 + v01.z * w01 + v11.z * w11;

            const int k = i * 3 + j;
            // wr layout [OC=3][IC=3][3][3]
            acc0 += wsh[0 * 27 + k] * vx + wsh[0 * 27 + 9 + k] * vy + wsh[0 * 27 + 18 + k] * vz;
            acc1 += wsh[1 * 27 + k] * vx + wsh[1 * 27 + 9 + k] * vy + wsh[1 * 27 + 18 + k] * vz;
            acc2 += wsh[2 * 27 + k] * vx + wsh[2 * 27 + 9 + k] * vy + wsh[2 * 27 + 18 + k] * vz;
        }
    }

    so[0][tx][ty] = acc0 + bsh[0];
    so[1][tx][ty] = acc1 + bsh[1];
    so[2][tx][ty] = acc2 + bsh[2];
    __syncthreads();

    // transposed store: w fastest within each 8-wide row
    for (int e = tid; e < 3 * 32 * 8; e += 256) {
        int oc = e >> 8;
        int r  = (e >> 3) & 31;
        int c  = e & 7;
        out[((size_t)(n * 3 + oc) * HH + h0 + r) * WW + w0 + c] = so[oc][r][c];
    }
}

// ---------------------------------------------------------------------------
extern "C" void kernel_launch(void* const* d_in, const int* in_sizes, int n_in,
                              void* d_out, int out_size)
{
    const float* x  = (const float*)d_in[0];
    const float* w1 = (const float*)d_in[1];
    const float* b1 = (const float*)d_in[2];
    const float* w2 = (const float*)d_in[3];
    const float* b2 = (const float*)d_in[4];
    const float* w3 = (const float*)d_in[5];
    const float* b3 = (const float*)d_in[6];
    const float* w4 = (const float*)d_in[7];
    const float* b4 = (const float*)d_in[8];
    const float* wr = (const float*)d_in[9];
    const float* br = (const float*)d_in[10];
    float* out = (float*)d_out;

    const dim3 cb(32, 8);
    const dim3 cg(WW / 128, HH / 8, NN);     // (5, 60, 4)

    pack_x_kernel<<<(NN * HH * WW + 255) / 256, 256>>>(x);

    conv5_kernel<3, 0, 1, false><<<cg, cb>>>(x, w1, b1);        // x  -> t1
    conv5_kernel<4, 1, 2, false><<<cg, cb>>>(nullptr, w2, b2);  // t1 -> t2
    conv5_kernel<4, 2, 1, false><<<cg, cb>>>(nullptr, w3, b3);  // t2 -> t1
    conv5_kernel<4, 1, 2, true ><<<cg, cb>>>(nullptr, w4, b4);  // t1 -> t2 (theta NHWC4)

    const dim3 sb(32, 8);
    const dim3 sg(HH / 32, WW / 8, NN);      // (15, 80, 4)
    stn_sample_kernel<<<sg, sb>>>(wr, br, out);
}